// round 1
// baseline (speedup 1.0000x reference)
#include <cuda_runtime.h>
#include <math.h>

#define DH 128
#define NMAX 100000
#define GMAX 512

// Scratch (static device globals — no runtime allocation)
__device__ float g_A[NMAX * DH];        // GEMM output / gather source
__device__ float g_B[NMAX * DH];        // scatter accumulator / next-layer input
__device__ float g_dinv[NMAX];
__device__ int   g_deg[NMAX];
__device__ float g_pooled[GMAX * DH];
__device__ int   g_cnt[GMAX];

// ---------------- reset: deg=1 (self loop), pooled=0, cnt=0 ----------------
__global__ void k_reset(int n, int g) {
    int idx = blockIdx.x * blockDim.x + threadIdx.x;
    if (idx < n) g_deg[idx] = 1;
    if (idx < g * DH) g_pooled[idx] = 0.0f;
    if (idx < g) g_cnt[idx] = 0;
}

// ---------------- degree count over col ----------------
__global__ void k_deg_count(const int* __restrict__ col, int E) {
    int e = blockIdx.x * blockDim.x + threadIdx.x;
    if (e < E) atomicAdd(&g_deg[col[e]], 1);
}

__global__ void k_dinv(int n) {
    int i = blockIdx.x * blockDim.x + threadIdx.x;
    if (i < n) g_dinv[i] = rsqrtf((float)g_deg[i]);
}

// ---------------- GEMM: Y[n,128] = X[n,128] @ W[128,128] ----------------
// BM=64 rows per block, full K=128, full N=128. 256 threads: 8 row-groups x 32 col-groups.
// Each thread computes 8 rows x 4 cols.
__global__ __launch_bounds__(256) void k_gemm(const float* __restrict__ X,
                                              const float* __restrict__ W,
                                              float* __restrict__ Y, int n) {
    extern __shared__ float smem[];
    float* Ws = smem;               // 128*128
    float* Xs = smem + DH * DH;     // 64*128

    int tid = threadIdx.x;
    const float4* W4 = reinterpret_cast<const float4*>(W);
    float4* Ws4 = reinterpret_cast<float4*>(Ws);
    #pragma unroll
    for (int i = tid; i < DH * DH / 4; i += 256) Ws4[i] = W4[i];

    int rowBase = blockIdx.x * 64;
    float4* Xs4 = reinterpret_cast<float4*>(Xs);
    const float4* X4 = reinterpret_cast<const float4*>(X);
    #pragma unroll
    for (int i = tid; i < 64 * DH / 4; i += 256) {
        int r = i / (DH / 4);
        int cc = i % (DH / 4);
        int gr = rowBase + r;
        Xs4[i] = (gr < n) ? X4[gr * (DH / 4) + cc] : make_float4(0.f, 0.f, 0.f, 0.f);
    }
    __syncthreads();

    int tx = tid & 31;   // col group: cols tx*4 .. tx*4+3
    int ty = tid >> 5;   // row group: rows ty*8 .. ty*8+7

    float acc[8][4] = {};
    #pragma unroll 4
    for (int k = 0; k < DH; ++k) {
        float4 b = *reinterpret_cast<const float4*>(&Ws[k * DH + (tx << 2)]);
        #pragma unroll
        for (int i = 0; i < 8; ++i) {
            float a = Xs[((ty << 3) + i) * DH + k];
            acc[i][0] = fmaf(a, b.x, acc[i][0]);
            acc[i][1] = fmaf(a, b.y, acc[i][1]);
            acc[i][2] = fmaf(a, b.z, acc[i][2]);
            acc[i][3] = fmaf(a, b.w, acc[i][3]);
        }
    }
    #pragma unroll
    for (int i = 0; i < 8; ++i) {
        int gr = rowBase + (ty << 3) + i;
        if (gr < n)
            *reinterpret_cast<float4*>(&Y[gr * DH + (tx << 2)]) =
                make_float4(acc[i][0], acc[i][1], acc[i][2], acc[i][3]);
    }
}

// ---------------- self-loop init: B[i,:] = A[i,:] * dinv[i]^2 ----------------
__global__ void k_selfinit(const float* __restrict__ A, float* __restrict__ B, int n) {
    int idx = blockIdx.x * blockDim.x + threadIdx.x;   // float4 index
    int total = n * (DH / 4);
    if (idx >= total) return;
    int node = idx >> 5;                  // DH/4 = 32 float4 per row
    float s = g_dinv[node];
    float s2 = s * s;
    float4 v = reinterpret_cast<const float4*>(A)[idx];
    v.x *= s2; v.y *= s2; v.z *= s2; v.w *= s2;
    reinterpret_cast<float4*>(B)[idx] = v;
}

// ---------------- edge scatter: B[c,:] += A[r,:] * dinv[r]*dinv[c] ----------------
// One warp per edge; lane handles 4 floats; vector red (16B) to L2.
__global__ void k_scatter(const float* __restrict__ A, float* __restrict__ B,
                          const int* __restrict__ row, const int* __restrict__ col,
                          int E) {
    int lane = threadIdx.x & 31;
    int e = (blockIdx.x * blockDim.x + threadIdx.x) >> 5;
    if (e >= E) return;
    int r = __ldg(&row[e]);
    int c = __ldg(&col[e]);
    float nm = __ldg(&g_dinv[r]) * __ldg(&g_dinv[c]);
    float4 v = __ldg(reinterpret_cast<const float4*>(A + (size_t)r * DH) + lane);
    v.x *= nm; v.y *= nm; v.z *= nm; v.w *= nm;
    float* p = B + (size_t)c * DH + (lane << 2);
    asm volatile("red.global.add.v4.f32 [%0], {%1, %2, %3, %4};"
                 :: "l"(p), "f"(v.x), "f"(v.y), "f"(v.z), "f"(v.w) : "memory");
}

// ---------------- bias + relu in place ----------------
__global__ void k_biasrelu(float* __restrict__ H, const float* __restrict__ b, int n) {
    int idx = blockIdx.x * blockDim.x + threadIdx.x;   // float4 index
    int total = n * (DH / 4);
    if (idx >= total) return;
    int j = idx & 31;
    float4 bb = reinterpret_cast<const float4*>(b)[j];
    float4 v = reinterpret_cast<float4*>(H)[idx];
    v.x = fmaxf(v.x + bb.x, 0.f);
    v.y = fmaxf(v.y + bb.y, 0.f);
    v.z = fmaxf(v.z + bb.z, 0.f);
    v.w = fmaxf(v.w + bb.w, 0.f);
    reinterpret_cast<float4*>(H)[idx] = v;
}

// ---------------- mean pool (sum via atomics; divide later) ----------------
__global__ void k_pool(const float* __restrict__ H, const int* __restrict__ batch, int n) {
    int lane = threadIdx.x & 31;
    int node = (blockIdx.x * blockDim.x + threadIdx.x) >> 5;
    if (node >= n) return;
    int b = __ldg(&batch[node]);
    float4 v = __ldg(reinterpret_cast<const float4*>(H + (size_t)node * DH) + lane);
    float* p = g_pooled + (size_t)b * DH + (lane << 2);
    asm volatile("red.global.add.v4.f32 [%0], {%1, %2, %3, %4};"
                 :: "l"(p), "f"(v.x), "f"(v.y), "f"(v.z), "f"(v.w) : "memory");
    if (lane == 0) atomicAdd(&g_cnt[b], 1);
}

// ---------------- head: logits = (pooled/cnt) @ Wout + bout; log_softmax ----------------
__global__ void k_head(const float* __restrict__ Wout, const float* __restrict__ bout,
                       float* __restrict__ out, int G) {
    int g = blockIdx.x * blockDim.x + threadIdx.x;
    if (g >= G) return;
    float inv = 1.0f / fmaxf((float)g_cnt[g], 1.0f);
    float logit[10];
    #pragma unroll
    for (int c = 0; c < 10; ++c) logit[c] = bout[c];
    for (int k = 0; k < DH; ++k) {
        float p = g_pooled[g * DH + k] * inv;
        #pragma unroll
        for (int c = 0; c < 10; ++c) logit[c] = fmaf(p, Wout[k * 10 + c], logit[c]);
    }
    float m = logit[0];
    #pragma unroll
    for (int c = 1; c < 10; ++c) m = fmaxf(m, logit[c]);
    float s = 0.f;
    #pragma unroll
    for (int c = 0; c < 10; ++c) s += expf(logit[c] - m);
    float lse = m + logf(s);
    #pragma unroll
    for (int c = 0; c < 10; ++c) out[g * 10 + c] = logit[c] - lse;
}

extern "C" void kernel_launch(void* const* d_in, const int* in_sizes, int n_in,
                              void* d_out, int out_size) {
    const float* x    = (const float*)d_in[0];
    const float* W1   = (const float*)d_in[1];
    const float* b1   = (const float*)d_in[2];
    const float* W2   = (const float*)d_in[3];
    const float* b2   = (const float*)d_in[4];
    const float* Wout = (const float*)d_in[5];
    const float* bout = (const float*)d_in[6];
    const int*   ei   = (const int*)d_in[7];
    const int*   batch= (const int*)d_in[8];
    float* out = (float*)d_out;

    int n = in_sizes[0] / DH;
    int E = in_sizes[7] / 2;
    int G = out_size / 10;
    const int* row = ei;
    const int* col = ei + E;

    float *A, *B;
    cudaGetSymbolAddress((void**)&A, g_A);
    cudaGetSymbolAddress((void**)&B, g_B);

    const int smemGemm = (DH * DH + 64 * DH) * sizeof(float);   // 96 KB
    cudaFuncSetAttribute(k_gemm, cudaFuncAttributeMaxDynamicSharedMemorySize, smemGemm);

    int resetTot = n > G * DH ? n : G * DH;
    k_reset<<<(resetTot + 255) / 256, 256>>>(n, G);
    k_deg_count<<<(E + 255) / 256, 256>>>(col, E);
    k_dinv<<<(n + 255) / 256, 256>>>(n);

    int gemmBlocks = (n + 63) / 64;
    int vec4 = n * (DH / 4);
    int scatterBlocks = (E * 32 + 255) / 256;
    int poolBlocks = (n * 32 + 255) / 256;

    // Layer 1
    k_gemm<<<gemmBlocks, 256, smemGemm>>>(x, W1, A, n);
    k_selfinit<<<(vec4 + 255) / 256, 256>>>(A, B, n);
    k_scatter<<<scatterBlocks, 256>>>(A, B, row, col, E);
    k_biasrelu<<<(vec4 + 255) / 256, 256>>>(B, b1, n);

    // Layer 2
    k_gemm<<<gemmBlocks, 256, smemGemm>>>(B, W2, A, n);
    k_selfinit<<<(vec4 + 255) / 256, 256>>>(A, B, n);
    k_scatter<<<scatterBlocks, 256>>>(A, B, row, col, E);
    k_biasrelu<<<(vec4 + 255) / 256, 256>>>(B, b2, n);

    // Pool + head
    k_pool<<<poolBlocks, 256>>>(B, batch, n);
    k_head<<<(G + 255) / 256, 256>>>(Wout, bout, out, G);
}

// round 2
// speedup vs baseline: 1.6703x; 1.6703x over previous
#include <cuda_runtime.h>
#include <math.h>

#define DH 128
#define NMAX 100000
#define EMAX 3200000
#define GMAX 512

// Scratch (static device globals — no runtime allocation)
__device__ float g_A[NMAX * DH];          // GEMM output / gather source
__device__ float g_B[NMAX * DH];          // gather output / next-layer input
__device__ float g_dinv[NMAX];
__device__ int   g_deg[NMAX];             // 1 + incoming edge count
__device__ int   g_rowptr[NMAX + 1];      // CSR-by-destination offsets
__device__ int   g_cursor[NMAX];
__device__ int   g_src[EMAX];             // source node per CSR slot
__device__ float g_pooled[GMAX * DH];
__device__ int   g_cnt[GMAX];

// ---------------- reset: deg=1 (self loop), pooled=0, cnt=0 ----------------
__global__ void k_reset(int n, int g) {
    int idx = blockIdx.x * blockDim.x + threadIdx.x;
    if (idx < n) g_deg[idx] = 1;
    if (idx < g * DH) g_pooled[idx] = 0.0f;
    if (idx < g) g_cnt[idx] = 0;
}

// ---------------- degree count over col ----------------
__global__ void k_deg_count(const int* __restrict__ col, int E) {
    int e = blockIdx.x * blockDim.x + threadIdx.x;
    if (e < E) atomicAdd(&g_deg[col[e]], 1);
}

__global__ void k_dinv(int n) {
    int i = blockIdx.x * blockDim.x + threadIdx.x;
    if (i < n) g_dinv[i] = rsqrtf((float)g_deg[i]);
}

// ---------------- single-block exclusive scan of (deg-1) -> rowptr, cursor ----
__global__ __launch_bounds__(1024) void k_scan(int n) {
    __shared__ int ssum[1024];
    int tid = threadIdx.x;
    int chunk = (n + 1023) / 1024;
    int lo = tid * chunk;
    int hi = lo + chunk; if (hi > n) hi = n;
    int s = 0;
    for (int i = lo; i < hi; ++i) s += g_deg[i] - 1;
    ssum[tid] = s;
    __syncthreads();
    // inclusive scan over thread sums
    for (int off = 1; off < 1024; off <<= 1) {
        int v = (tid >= off) ? ssum[tid - off] : 0;
        __syncthreads();
        ssum[tid] += v;
        __syncthreads();
    }
    int run = ssum[tid] - s;   // exclusive prefix for this thread's chunk
    for (int i = lo; i < hi; ++i) {
        g_rowptr[i] = run;
        g_cursor[i] = run;
        run += g_deg[i] - 1;
    }
    if (tid == 1023) g_rowptr[n] = ssum[1023];
}

// ---------------- fill CSR: slot = cursor[c]++ ; src[slot] = r ----------------
__global__ void k_fill(const int* __restrict__ row, const int* __restrict__ col, int E) {
    int e = blockIdx.x * blockDim.x + threadIdx.x;
    if (e >= E) return;
    int r = __ldg(&row[e]);
    int c = __ldg(&col[e]);
    int pos = atomicAdd(&g_cursor[c], 1);
    g_src[pos] = r;
}

// ---------------- GEMM: Y[n,128] = X[n,128] @ W[128,128] ----------------
__global__ __launch_bounds__(256) void k_gemm(const float* __restrict__ X,
                                              const float* __restrict__ W,
                                              float* __restrict__ Y, int n) {
    extern __shared__ float smem[];
    float* Ws = smem;               // 128*128
    float* Xs = smem + DH * DH;     // 64*128

    int tid = threadIdx.x;
    const float4* W4 = reinterpret_cast<const float4*>(W);
    float4* Ws4 = reinterpret_cast<float4*>(Ws);
    #pragma unroll
    for (int i = tid; i < DH * DH / 4; i += 256) Ws4[i] = W4[i];

    int rowBase = blockIdx.x * 64;
    float4* Xs4 = reinterpret_cast<float4*>(Xs);
    const float4* X4 = reinterpret_cast<const float4*>(X);
    #pragma unroll
    for (int i = tid; i < 64 * DH / 4; i += 256) {
        int r = i / (DH / 4);
        int cc = i % (DH / 4);
        int gr = rowBase + r;
        Xs4[i] = (gr < n) ? X4[gr * (DH / 4) + cc] : make_float4(0.f, 0.f, 0.f, 0.f);
    }
    __syncthreads();

    int tx = tid & 31;   // col group
    int ty = tid >> 5;   // row group

    float acc[8][4] = {};
    #pragma unroll 4
    for (int k = 0; k < DH; ++k) {
        float4 b = *reinterpret_cast<const float4*>(&Ws[k * DH + (tx << 2)]);
        #pragma unroll
        for (int i = 0; i < 8; ++i) {
            float a = Xs[((ty << 3) + i) * DH + k];
            acc[i][0] = fmaf(a, b.x, acc[i][0]);
            acc[i][1] = fmaf(a, b.y, acc[i][1]);
            acc[i][2] = fmaf(a, b.z, acc[i][2]);
            acc[i][3] = fmaf(a, b.w, acc[i][3]);
        }
    }
    #pragma unroll
    for (int i = 0; i < 8; ++i) {
        int gr = rowBase + (ty << 3) + i;
        if (gr < n)
            *reinterpret_cast<float4*>(&Y[gr * DH + (tx << 2)]) =
                make_float4(acc[i][0], acc[i][1], acc[i][2], acc[i][3]);
    }
}

// ---------------- fused gather: B[c,:] = relu_opt( sum_in + selfloop + bias ) --
// One warp per destination node; lane owns a float4 column slice.
__global__ __launch_bounds__(256) void k_gather(const float* __restrict__ A,
                                                float* __restrict__ B,
                                                const float* __restrict__ bias,
                                                int n, int doRelu) {
    int lane = threadIdx.x & 31;
    int node = (blockIdx.x * blockDim.x + threadIdx.x) >> 5;
    if (node >= n) return;

    const float4* A4 = reinterpret_cast<const float4*>(A);
    float dc = __ldg(&g_dinv[node]);

    // self loop: A[node] * dinv^2
    float4 acc = __ldg(&A4[(size_t)node * 32 + lane]);
    float s2 = dc * dc;
    acc.x *= s2; acc.y *= s2; acc.z *= s2; acc.w *= s2;

    int e = g_rowptr[node];
    int end = g_rowptr[node + 1];

    // 4-way unrolled edge loop for MLP
    for (; e + 4 <= end; e += 4) {
        int r0 = __ldg(&g_src[e + 0]);
        int r1 = __ldg(&g_src[e + 1]);
        int r2 = __ldg(&g_src[e + 2]);
        int r3 = __ldg(&g_src[e + 3]);
        float nm0 = dc * __ldg(&g_dinv[r0]);
        float nm1 = dc * __ldg(&g_dinv[r1]);
        float nm2 = dc * __ldg(&g_dinv[r2]);
        float nm3 = dc * __ldg(&g_dinv[r3]);
        float4 v0 = __ldg(&A4[(size_t)r0 * 32 + lane]);
        float4 v1 = __ldg(&A4[(size_t)r1 * 32 + lane]);
        float4 v2 = __ldg(&A4[(size_t)r2 * 32 + lane]);
        float4 v3 = __ldg(&A4[(size_t)r3 * 32 + lane]);
        acc.x = fmaf(v0.x, nm0, acc.x); acc.y = fmaf(v0.y, nm0, acc.y);
        acc.z = fmaf(v0.z, nm0, acc.z); acc.w = fmaf(v0.w, nm0, acc.w);
        acc.x = fmaf(v1.x, nm1, acc.x); acc.y = fmaf(v1.y, nm1, acc.y);
        acc.z = fmaf(v1.z, nm1, acc.z); acc.w = fmaf(v1.w, nm1, acc.w);
        acc.x = fmaf(v2.x, nm2, acc.x); acc.y = fmaf(v2.y, nm2, acc.y);
        acc.z = fmaf(v2.z, nm2, acc.z); acc.w = fmaf(v2.w, nm2, acc.w);
        acc.x = fmaf(v3.x, nm3, acc.x); acc.y = fmaf(v3.y, nm3, acc.y);
        acc.z = fmaf(v3.z, nm3, acc.z); acc.w = fmaf(v3.w, nm3, acc.w);
    }
    for (; e < end; ++e) {
        int r = __ldg(&g_src[e]);
        float nm = dc * __ldg(&g_dinv[r]);
        float4 v = __ldg(&A4[(size_t)r * 32 + lane]);
        acc.x = fmaf(v.x, nm, acc.x); acc.y = fmaf(v.y, nm, acc.y);
        acc.z = fmaf(v.z, nm, acc.z); acc.w = fmaf(v.w, nm, acc.w);
    }

    float4 bb = __ldg(reinterpret_cast<const float4*>(bias) + lane);
    acc.x += bb.x; acc.y += bb.y; acc.z += bb.z; acc.w += bb.w;
    if (doRelu) {
        acc.x = fmaxf(acc.x, 0.f); acc.y = fmaxf(acc.y, 0.f);
        acc.z = fmaxf(acc.z, 0.f); acc.w = fmaxf(acc.w, 0.f);
    }
    reinterpret_cast<float4*>(B)[(size_t)node * 32 + lane] = acc;
}

// ---------------- mean pool (sum via atomics; divide in head) ----------------
__global__ void k_pool(const float* __restrict__ H, const int* __restrict__ batch, int n) {
    int lane = threadIdx.x & 31;
    int node = (blockIdx.x * blockDim.x + threadIdx.x) >> 5;
    if (node >= n) return;
    int b = __ldg(&batch[node]);
    float4 v = __ldg(reinterpret_cast<const float4*>(H + (size_t)node * DH) + lane);
    float* p = g_pooled + (size_t)b * DH + (lane << 2);
    asm volatile("red.global.add.v4.f32 [%0], {%1, %2, %3, %4};"
                 :: "l"(p), "f"(v.x), "f"(v.y), "f"(v.z), "f"(v.w) : "memory");
    if (lane == 0) atomicAdd(&g_cnt[b], 1);
}

// ---------------- head: logits = (pooled/cnt) @ Wout + bout; log_softmax -----
__global__ void k_head(const float* __restrict__ Wout, const float* __restrict__ bout,
                       float* __restrict__ out, int G) {
    int g = blockIdx.x * blockDim.x + threadIdx.x;
    if (g >= G) return;
    float inv = 1.0f / fmaxf((float)g_cnt[g], 1.0f);
    float logit[10];
    #pragma unroll
    for (int c = 0; c < 10; ++c) logit[c] = bout[c];
    for (int k = 0; k < DH; ++k) {
        float p = g_pooled[g * DH + k] * inv;
        #pragma unroll
        for (int c = 0; c < 10; ++c) logit[c] = fmaf(p, Wout[k * 10 + c], logit[c]);
    }
    float m = logit[0];
    #pragma unroll
    for (int c = 1; c < 10; ++c) m = fmaxf(m, logit[c]);
    float s = 0.f;
    #pragma unroll
    for (int c = 0; c < 10; ++c) s += expf(logit[c] - m);
    float lse = m + logf(s);
    #pragma unroll
    for (int c = 0; c < 10; ++c) out[g * 10 + c] = logit[c] - lse;
}

extern "C" void kernel_launch(void* const* d_in, const int* in_sizes, int n_in,
                              void* d_out, int out_size) {
    const float* x    = (const float*)d_in[0];
    const float* W1   = (const float*)d_in[1];
    const float* b1   = (const float*)d_in[2];
    const float* W2   = (const float*)d_in[3];
    const float* b2   = (const float*)d_in[4];
    const float* Wout = (const float*)d_in[5];
    const float* bout = (const float*)d_in[6];
    const int*   ei   = (const int*)d_in[7];
    const int*   batch= (const int*)d_in[8];
    float* out = (float*)d_out;

    int n = in_sizes[0] / DH;
    int E = in_sizes[7] / 2;
    int G = out_size / 10;
    const int* row = ei;
    const int* col = ei + E;

    float *A, *B;
    cudaGetSymbolAddress((void**)&A, g_A);
    cudaGetSymbolAddress((void**)&B, g_B);

    const int smemGemm = (DH * DH + 64 * DH) * sizeof(float);   // 96 KB
    cudaFuncSetAttribute(k_gemm, cudaFuncAttributeMaxDynamicSharedMemorySize, smemGemm);

    // ---- graph preprocessing (CSR by destination) ----
    int resetTot = n > G * DH ? n : G * DH;
    k_reset<<<(resetTot + 255) / 256, 256>>>(n, G);
    k_deg_count<<<(E + 255) / 256, 256>>>(col, E);
    k_dinv<<<(n + 255) / 256, 256>>>(n);
    k_scan<<<1, 1024>>>(n);
    k_fill<<<(E + 255) / 256, 256>>>(row, col, E);

    int gemmBlocks = (n + 63) / 64;
    int warpBlocks = (n * 32 + 255) / 256;

    // Layer 1
    k_gemm<<<gemmBlocks, 256, smemGemm>>>(x, W1, A, n);
    k_gather<<<warpBlocks, 256>>>(A, B, b1, n, 1);

    // Layer 2
    k_gemm<<<gemmBlocks, 256, smemGemm>>>(B, W2, A, n);
    k_gather<<<warpBlocks, 256>>>(A, B, b2, n, 1);

    // Pool + head
    k_pool<<<warpBlocks, 256>>>(B, batch, n);
    k_head<<<(G + 255) / 256, 256>>>(Wout, bout, out, G);
}

// round 3
// speedup vs baseline: 2.2093x; 1.3227x over previous
#include <cuda_runtime.h>
#include <math.h>

#define DH 128
#define NMAX 100000
#define EMAX 3200000
#define GMAX 512
#define SCAN_TILE 1024
#define NBMAX ((NMAX + SCAN_TILE - 1) / SCAN_TILE)   // 98

// Scratch (static device globals — no runtime allocation)
__device__ float g_A[NMAX * DH];          // GEMM output / gather source
__device__ float g_B[NMAX * DH];          // gather output / next-layer input
__device__ float g_dinv[NMAX];
__device__ int   g_deg[NMAX];             // 1 + incoming edge count
__device__ int   g_rowptr[NMAX + 1];      // CSR-by-destination offsets
__device__ int   g_cursor[NMAX];
__device__ int   g_src[EMAX];             // source node per CSR slot
__device__ int   g_bsum[NBMAX + 32];
__device__ int   g_boff[NBMAX + 32];
__device__ float g_pooled[GMAX * DH];
__device__ int   g_cnt[GMAX];

// ---------------- reset: deg=1 (self loop), pooled=0, cnt=0 ----------------
__global__ void k_reset(int n, int g) {
    int idx = blockIdx.x * blockDim.x + threadIdx.x;
    if (idx < n) g_deg[idx] = 1;
    if (idx < g * DH) g_pooled[idx] = 0.0f;
    if (idx < g) g_cnt[idx] = 0;
}

// ---------------- degree count over col ----------------
__global__ void k_deg_count(const int* __restrict__ col, int E) {
    int e = blockIdx.x * blockDim.x + threadIdx.x;
    if (e < E) atomicAdd(&g_deg[col[e]], 1);
}

__global__ void k_dinv(int n) {
    int i = blockIdx.x * blockDim.x + threadIdx.x;
    if (i < n) g_dinv[i] = rsqrtf((float)g_deg[i]);
}

// ---------------- 3-phase scan of (deg-1) -> rowptr, cursor ----------------
// Phase A: per-block sums over 1024-element tiles (256 thr x 4 elems)
__global__ __launch_bounds__(256) void k_scanA(int n) {
    int base = blockIdx.x * SCAN_TILE;
    int tid = threadIdx.x;
    int s = 0;
    #pragma unroll
    for (int j = 0; j < 4; ++j) {
        int i = base + tid * 4 + j;
        if (i < n) s += g_deg[i] - 1;
    }
    #pragma unroll
    for (int o = 16; o; o >>= 1) s += __shfl_down_sync(~0u, s, o);
    __shared__ int ws[8];
    if ((tid & 31) == 0) ws[tid >> 5] = s;
    __syncthreads();
    if (tid < 8) {
        int v = ws[tid];
        #pragma unroll
        for (int o = 4; o; o >>= 1) v += __shfl_down_sync(0xff, v, o);
        if (tid == 0) g_bsum[blockIdx.x] = v;
    }
}

// Phase B: 1-block exclusive scan of block sums (nb <= 128); writes rowptr[n]=total
__global__ __launch_bounds__(128) void k_scanB(int nb, int n) {
    int tid = threadIdx.x;
    int s = (tid < nb) ? g_bsum[tid] : 0;
    int lane = tid & 31, wid = tid >> 5;
    int x = s;
    #pragma unroll
    for (int o = 1; o < 32; o <<= 1) {
        int y = __shfl_up_sync(~0u, x, o);
        if (lane >= o) x += y;
    }
    __shared__ int ws[4];
    if (lane == 31) ws[wid] = x;
    __syncthreads();
    if (tid < 4) {
        int y = ws[tid];
        #pragma unroll
        for (int o = 1; o < 4; o <<= 1) {
            int z = __shfl_up_sync(0xf, y, o);
            if (tid >= o) y += z;
        }
        ws[tid] = y;
    }
    __syncthreads();
    int incl = x + (wid ? ws[wid - 1] : 0);
    if (tid < nb) g_boff[tid] = incl - s;          // exclusive block offset
    if (tid == 127) g_rowptr[n] = ws[3];           // grand total
}

// Phase C: block-local exclusive scan + offset, write rowptr & cursor
__global__ __launch_bounds__(256) void k_scanC(int n) {
    int base = blockIdx.x * SCAN_TILE;
    int tid = threadIdx.x;
    int lane = tid & 31, wid = tid >> 5;
    int v[4], s = 0;
    #pragma unroll
    for (int j = 0; j < 4; ++j) {
        int i = base + tid * 4 + j;
        v[j] = (i < n) ? g_deg[i] - 1 : 0;
        s += v[j];
    }
    int x = s;
    #pragma unroll
    for (int o = 1; o < 32; o <<= 1) {
        int y = __shfl_up_sync(~0u, x, o);
        if (lane >= o) x += y;
    }
    __shared__ int ws[8];
    if (lane == 31) ws[wid] = x;
    __syncthreads();
    if (tid < 8) {
        int y = ws[tid];
        #pragma unroll
        for (int o = 1; o < 8; o <<= 1) {
            int z = __shfl_up_sync(0xff, y, o);
            if (tid >= o) y += z;
        }
        ws[tid] = y;
    }
    __syncthreads();
    int excl = x - s + (wid ? ws[wid - 1] : 0) + g_boff[blockIdx.x];
    #pragma unroll
    for (int j = 0; j < 4; ++j) {
        int i = base + tid * 4 + j;
        if (i < n) {
            g_rowptr[i] = excl;
            g_cursor[i] = excl;
            excl += v[j];
        }
    }
}

// ---------------- fill CSR: slot = cursor[c]++ ; src[slot] = r ----------------
__global__ void k_fill(const int* __restrict__ row, const int* __restrict__ col, int E) {
    int e = blockIdx.x * blockDim.x + threadIdx.x;
    if (e >= E) return;
    int r = __ldg(&row[e]);
    int c = __ldg(&col[e]);
    int pos = atomicAdd(&g_cursor[c], 1);
    g_src[pos] = r;
}

// ---------------- GEMM: Y[n,128] = X[n,128] @ W[128,128] ----------------
__global__ __launch_bounds__(256) void k_gemm(const float* __restrict__ X,
                                              const float* __restrict__ W,
                                              float* __restrict__ Y, int n) {
    extern __shared__ float smem[];
    float* Ws = smem;               // 128*128
    float* Xs = smem + DH * DH;     // 64*128

    int tid = threadIdx.x;
    const float4* W4 = reinterpret_cast<const float4*>(W);
    float4* Ws4 = reinterpret_cast<float4*>(Ws);
    #pragma unroll
    for (int i = tid; i < DH * DH / 4; i += 256) Ws4[i] = W4[i];

    int rowBase = blockIdx.x * 64;
    float4* Xs4 = reinterpret_cast<float4*>(Xs);
    const float4* X4 = reinterpret_cast<const float4*>(X);
    #pragma unroll
    for (int i = tid; i < 64 * DH / 4; i += 256) {
        int r = i / (DH / 4);
        int cc = i % (DH / 4);
        int gr = rowBase + r;
        Xs4[i] = (gr < n) ? X4[gr * (DH / 4) + cc] : make_float4(0.f, 0.f, 0.f, 0.f);
    }
    __syncthreads();

    int tx = tid & 31;   // col group
    int ty = tid >> 5;   // row group

    float acc[8][4] = {};
    #pragma unroll 4
    for (int k = 0; k < DH; ++k) {
        float4 b = *reinterpret_cast<const float4*>(&Ws[k * DH + (tx << 2)]);
        #pragma unroll
        for (int i = 0; i < 8; ++i) {
            float a = Xs[((ty << 3) + i) * DH + k];
            acc[i][0] = fmaf(a, b.x, acc[i][0]);
            acc[i][1] = fmaf(a, b.y, acc[i][1]);
            acc[i][2] = fmaf(a, b.z, acc[i][2]);
            acc[i][3] = fmaf(a, b.w, acc[i][3]);
        }
    }
    #pragma unroll
    for (int i = 0; i < 8; ++i) {
        int gr = rowBase + (ty << 3) + i;
        if (gr < n)
            *reinterpret_cast<float4*>(&Y[gr * DH + (tx << 2)]) =
                make_float4(acc[i][0], acc[i][1], acc[i][2], acc[i][3]);
    }
}

// ---------------- fused gather: B[c,:] = relu_opt( sum_in + selfloop + bias ) --
__global__ __launch_bounds__(256) void k_gather(const float* __restrict__ A,
                                                float* __restrict__ B,
                                                const float* __restrict__ bias,
                                                int n, int doRelu) {
    int lane = threadIdx.x & 31;
    int node = (blockIdx.x * blockDim.x + threadIdx.x) >> 5;
    if (node >= n) return;

    const float4* A4 = reinterpret_cast<const float4*>(A);
    float dc = __ldg(&g_dinv[node]);

    float4 acc = __ldg(&A4[(size_t)node * 32 + lane]);
    float s2 = dc * dc;
    acc.x *= s2; acc.y *= s2; acc.z *= s2; acc.w *= s2;

    int e = g_rowptr[node];
    int end = g_rowptr[node + 1];

    for (; e + 4 <= end; e += 4) {
        int r0 = __ldg(&g_src[e + 0]);
        int r1 = __ldg(&g_src[e + 1]);
        int r2 = __ldg(&g_src[e + 2]);
        int r3 = __ldg(&g_src[e + 3]);
        float nm0 = dc * __ldg(&g_dinv[r0]);
        float nm1 = dc * __ldg(&g_dinv[r1]);
        float nm2 = dc * __ldg(&g_dinv[r2]);
        float nm3 = dc * __ldg(&g_dinv[r3]);
        float4 v0 = __ldg(&A4[(size_t)r0 * 32 + lane]);
        float4 v1 = __ldg(&A4[(size_t)r1 * 32 + lane]);
        float4 v2 = __ldg(&A4[(size_t)r2 * 32 + lane]);
        float4 v3 = __ldg(&A4[(size_t)r3 * 32 + lane]);
        acc.x = fmaf(v0.x, nm0, acc.x); acc.y = fmaf(v0.y, nm0, acc.y);
        acc.z = fmaf(v0.z, nm0, acc.z); acc.w = fmaf(v0.w, nm0, acc.w);
        acc.x = fmaf(v1.x, nm1, acc.x); acc.y = fmaf(v1.y, nm1, acc.y);
        acc.z = fmaf(v1.z, nm1, acc.z); acc.w = fmaf(v1.w, nm1, acc.w);
        acc.x = fmaf(v2.x, nm2, acc.x); acc.y = fmaf(v2.y, nm2, acc.y);
        acc.z = fmaf(v2.z, nm2, acc.z); acc.w = fmaf(v2.w, nm2, acc.w);
        acc.x = fmaf(v3.x, nm3, acc.x); acc.y = fmaf(v3.y, nm3, acc.y);
        acc.z = fmaf(v3.z, nm3, acc.z); acc.w = fmaf(v3.w, nm3, acc.w);
    }
    for (; e < end; ++e) {
        int r = __ldg(&g_src[e]);
        float nm = dc * __ldg(&g_dinv[r]);
        float4 v = __ldg(&A4[(size_t)r * 32 + lane]);
        acc.x = fmaf(v.x, nm, acc.x); acc.y = fmaf(v.y, nm, acc.y);
        acc.z = fmaf(v.z, nm, acc.z); acc.w = fmaf(v.w, nm, acc.w);
    }

    float4 bb = __ldg(reinterpret_cast<const float4*>(bias) + lane);
    acc.x += bb.x; acc.y += bb.y; acc.z += bb.z; acc.w += bb.w;
    if (doRelu) {
        acc.x = fmaxf(acc.x, 0.f); acc.y = fmaxf(acc.y, 0.f);
        acc.z = fmaxf(acc.z, 0.f); acc.w = fmaxf(acc.w, 0.f);
    }
    reinterpret_cast<float4*>(B)[(size_t)node * 32 + lane] = acc;
}

// ---------------- mean pool (sum via atomics; divide in head) ----------------
__global__ void k_pool(const float* __restrict__ H, const int* __restrict__ batch, int n) {
    int lane = threadIdx.x & 31;
    int node = (blockIdx.x * blockDim.x + threadIdx.x) >> 5;
    if (node >= n) return;
    int b = __ldg(&batch[node]);
    float4 v = __ldg(reinterpret_cast<const float4*>(H + (size_t)node * DH) + lane);
    float* p = g_pooled + (size_t)b * DH + (lane << 2);
    asm volatile("red.global.add.v4.f32 [%0], {%1, %2, %3, %4};"
                 :: "l"(p), "f"(v.x), "f"(v.y), "f"(v.z), "f"(v.w) : "memory");
    if (lane == 0) atomicAdd(&g_cnt[b], 1);
}

// ---------------- head: logits = (pooled/cnt) @ Wout + bout; log_softmax -----
__global__ void k_head(const float* __restrict__ Wout, const float* __restrict__ bout,
                       float* __restrict__ out, int G) {
    int g = blockIdx.x * blockDim.x + threadIdx.x;
    if (g >= G) return;
    float inv = 1.0f / fmaxf((float)g_cnt[g], 1.0f);
    float logit[10];
    #pragma unroll
    for (int c = 0; c < 10; ++c) logit[c] = bout[c];
    for (int k = 0; k < DH; ++k) {
        float p = g_pooled[g * DH + k] * inv;
        #pragma unroll
        for (int c = 0; c < 10; ++c) logit[c] = fmaf(p, Wout[k * 10 + c], logit[c]);
    }
    float m = logit[0];
    #pragma unroll
    for (int c = 1; c < 10; ++c) m = fmaxf(m, logit[c]);
    float s = 0.f;
    #pragma unroll
    for (int c = 0; c < 10; ++c) s += expf(logit[c] - m);
    float lse = m + logf(s);
    #pragma unroll
    for (int c = 0; c < 10; ++c) out[g * 10 + c] = logit[c] - lse;
}

extern "C" void kernel_launch(void* const* d_in, const int* in_sizes, int n_in,
                              void* d_out, int out_size) {
    const float* x    = (const float*)d_in[0];
    const float* W1   = (const float*)d_in[1];
    const float* b1   = (const float*)d_in[2];
    const float* W2   = (const float*)d_in[3];
    const float* b2   = (const float*)d_in[4];
    const float* Wout = (const float*)d_in[5];
    const float* bout = (const float*)d_in[6];
    const int*   ei   = (const int*)d_in[7];
    const int*   batch= (const int*)d_in[8];
    float* out = (float*)d_out;

    int n = in_sizes[0] / DH;
    int E = in_sizes[7] / 2;
    int G = out_size / 10;
    const int* row = ei;
    const int* col = ei + E;

    float *A, *B;
    cudaGetSymbolAddress((void**)&A, g_A);
    cudaGetSymbolAddress((void**)&B, g_B);

    const int smemGemm = (DH * DH + 64 * DH) * sizeof(float);   // 96 KB
    cudaFuncSetAttribute(k_gemm, cudaFuncAttributeMaxDynamicSharedMemorySize, smemGemm);

    // ---- graph preprocessing (CSR by destination) ----
    int resetTot = n > G * DH ? n : G * DH;
    k_reset<<<(resetTot + 255) / 256, 256>>>(n, G);
    k_deg_count<<<(E + 255) / 256, 256>>>(col, E);
    k_dinv<<<(n + 255) / 256, 256>>>(n);

    int nb = (n + SCAN_TILE - 1) / SCAN_TILE;
    k_scanA<<<nb, 256>>>(n);
    k_scanB<<<1, 128>>>(nb, n);
    k_scanC<<<nb, 256>>>(n);
    k_fill<<<(E + 255) / 256, 256>>>(row, col, E);

    int gemmBlocks = (n + 63) / 64;
    int warpBlocks = (n * 32 + 255) / 256;

    // Layer 1
    k_gemm<<<gemmBlocks, 256, smemGemm>>>(x, W1, A, n);
    k_gather<<<warpBlocks, 256>>>(A, B, b1, n, 1);

    // Layer 2
    k_gemm<<<gemmBlocks, 256, smemGemm>>>(B, W2, A, n);
    k_gather<<<warpBlocks, 256>>>(A, B, b2, n, 1);

    // Pool + head
    k_pool<<<warpBlocks, 256>>>(B, batch, n);
    k_head<<<(G + 255) / 256, 256>>>(Wout, bout, out, G);
}

// round 4
// speedup vs baseline: 2.4439x; 1.1062x over previous
#include <cuda_runtime.h>
#include <cuda_bf16.h>
#include <math.h>

#define DH 128
#define NMAX 100000
#define EMAX 3200000
#define GMAX 512
#define SCAN_TILE 1024
#define NBMAX ((NMAX + SCAN_TILE - 1) / SCAN_TILE)   // 98

// Scratch (static device globals — no runtime allocation)
__device__ __nv_bfloat16 g_Abf[NMAX * DH];  // GEMM output * dinv[row], bf16
__device__ float g_B[NMAX * DH];            // gather output / next-layer input
__device__ float g_dinv[NMAX];
__device__ int   g_deg[NMAX];               // 1 + incoming edge count
__device__ int   g_rowptr[NMAX + 1];        // CSR-by-destination offsets
__device__ int   g_cursor[NMAX];
__device__ int   g_src[EMAX];               // source node per CSR slot
__device__ int   g_bsum[NBMAX + 32];
__device__ int   g_boff[NBMAX + 32];
__device__ float g_pooled[GMAX * DH];
__device__ int   g_cnt[GMAX];

// ---------------- reset: deg=1 (self loop), pooled=0, cnt=0 ----------------
__global__ void k_reset(int n, int g) {
    int idx = blockIdx.x * blockDim.x + threadIdx.x;
    if (idx < n) g_deg[idx] = 1;
    if (idx < g * DH) g_pooled[idx] = 0.0f;
    if (idx < g) g_cnt[idx] = 0;
}

// ---------------- degree count over col ----------------
__global__ void k_deg_count(const int* __restrict__ col, int E) {
    int e = blockIdx.x * blockDim.x + threadIdx.x;
    if (e < E) atomicAdd(&g_deg[col[e]], 1);
}

__global__ void k_dinv(int n) {
    int i = blockIdx.x * blockDim.x + threadIdx.x;
    if (i < n) g_dinv[i] = rsqrtf((float)g_deg[i]);
}

// ---------------- 3-phase scan of (deg-1) -> rowptr, cursor ----------------
__global__ __launch_bounds__(256) void k_scanA(int n) {
    int base = blockIdx.x * SCAN_TILE;
    int tid = threadIdx.x;
    int s = 0;
    #pragma unroll
    for (int j = 0; j < 4; ++j) {
        int i = base + tid * 4 + j;
        if (i < n) s += g_deg[i] - 1;
    }
    #pragma unroll
    for (int o = 16; o; o >>= 1) s += __shfl_down_sync(~0u, s, o);
    __shared__ int ws[8];
    if ((tid & 31) == 0) ws[tid >> 5] = s;
    __syncthreads();
    if (tid < 8) {
        int v = ws[tid];
        #pragma unroll
        for (int o = 4; o; o >>= 1) v += __shfl_down_sync(0xff, v, o);
        if (tid == 0) g_bsum[blockIdx.x] = v;
    }
}

__global__ __launch_bounds__(128) void k_scanB(int nb, int n) {
    int tid = threadIdx.x;
    int s = (tid < nb) ? g_bsum[tid] : 0;
    int lane = tid & 31, wid = tid >> 5;
    int x = s;
    #pragma unroll
    for (int o = 1; o < 32; o <<= 1) {
        int y = __shfl_up_sync(~0u, x, o);
        if (lane >= o) x += y;
    }
    __shared__ int ws[4];
    if (lane == 31) ws[wid] = x;
    __syncthreads();
    if (tid < 4) {
        int y = ws[tid];
        #pragma unroll
        for (int o = 1; o < 4; o <<= 1) {
            int z = __shfl_up_sync(0xf, y, o);
            if (tid >= o) y += z;
        }
        ws[tid] = y;
    }
    __syncthreads();
    int incl = x + (wid ? ws[wid - 1] : 0);
    if (tid < nb) g_boff[tid] = incl - s;
    if (tid == 127) g_rowptr[n] = ws[3];
}

__global__ __launch_bounds__(256) void k_scanC(int n) {
    int base = blockIdx.x * SCAN_TILE;
    int tid = threadIdx.x;
    int lane = tid & 31, wid = tid >> 5;
    int v[4], s = 0;
    #pragma unroll
    for (int j = 0; j < 4; ++j) {
        int i = base + tid * 4 + j;
        v[j] = (i < n) ? g_deg[i] - 1 : 0;
        s += v[j];
    }
    int x = s;
    #pragma unroll
    for (int o = 1; o < 32; o <<= 1) {
        int y = __shfl_up_sync(~0u, x, o);
        if (lane >= o) x += y;
    }
    __shared__ int ws[8];
    if (lane == 31) ws[wid] = x;
    __syncthreads();
    if (tid < 8) {
        int y = ws[tid];
        #pragma unroll
        for (int o = 1; o < 8; o <<= 1) {
            int z = __shfl_up_sync(0xff, y, o);
            if (tid >= o) y += z;
        }
        ws[tid] = y;
    }
    __syncthreads();
    int excl = x - s + (wid ? ws[wid - 1] : 0) + g_boff[blockIdx.x];
    #pragma unroll
    for (int j = 0; j < 4; ++j) {
        int i = base + tid * 4 + j;
        if (i < n) {
            g_rowptr[i] = excl;
            g_cursor[i] = excl;
            excl += v[j];
        }
    }
}

// ---------------- fill CSR: slot = cursor[c]++ ; src[slot] = r ----------------
__global__ void k_fill(const int* __restrict__ row, const int* __restrict__ col, int E) {
    int e = blockIdx.x * blockDim.x + threadIdx.x;
    if (e >= E) return;
    int r = __ldg(&row[e]);
    int c = __ldg(&col[e]);
    int pos = atomicAdd(&g_cursor[c], 1);
    g_src[pos] = r;
}

// ------- GEMM: Abf[n,128] = bf16( (X[n,128] @ W[128,128]) * dinv[row] ) -------
__global__ __launch_bounds__(256) void k_gemm(const float* __restrict__ X,
                                              const float* __restrict__ W,
                                              __nv_bfloat16* __restrict__ Y, int n) {
    extern __shared__ float smem[];
    float* Ws = smem;               // 128*128
    float* Xs = smem + DH * DH;     // 64*128

    int tid = threadIdx.x;
    const float4* W4 = reinterpret_cast<const float4*>(W);
    float4* Ws4 = reinterpret_cast<float4*>(Ws);
    #pragma unroll
    for (int i = tid; i < DH * DH / 4; i += 256) Ws4[i] = W4[i];

    int rowBase = blockIdx.x * 64;
    float4* Xs4 = reinterpret_cast<float4*>(Xs);
    const float4* X4 = reinterpret_cast<const float4*>(X);
    #pragma unroll
    for (int i = tid; i < 64 * DH / 4; i += 256) {
        int r = i / (DH / 4);
        int cc = i % (DH / 4);
        int gr = rowBase + r;
        Xs4[i] = (gr < n) ? X4[gr * (DH / 4) + cc] : make_float4(0.f, 0.f, 0.f, 0.f);
    }
    __syncthreads();

    int tx = tid & 31;   // col group (cols tx*4..tx*4+3)
    int ty = tid >> 5;   // row group (rows ty*8..ty*8+7)

    float acc[8][4] = {};
    #pragma unroll 4
    for (int k = 0; k < DH; ++k) {
        float4 b = *reinterpret_cast<const float4*>(&Ws[k * DH + (tx << 2)]);
        #pragma unroll
        for (int i = 0; i < 8; ++i) {
            float a = Xs[((ty << 3) + i) * DH + k];
            acc[i][0] = fmaf(a, b.x, acc[i][0]);
            acc[i][1] = fmaf(a, b.y, acc[i][1]);
            acc[i][2] = fmaf(a, b.z, acc[i][2]);
            acc[i][3] = fmaf(a, b.w, acc[i][3]);
        }
    }
    #pragma unroll
    for (int i = 0; i < 8; ++i) {
        int gr = rowBase + (ty << 3) + i;
        if (gr < n) {
            float s = __ldg(&g_dinv[gr]);
            __nv_bfloat162 p0 = __floats2bfloat162_rn(acc[i][0] * s, acc[i][1] * s);
            __nv_bfloat162 p1 = __floats2bfloat162_rn(acc[i][2] * s, acc[i][3] * s);
            uint2 o;
            o.x = *reinterpret_cast<unsigned int*>(&p0);
            o.y = *reinterpret_cast<unsigned int*>(&p1);
            reinterpret_cast<uint2*>(Y)[(size_t)gr * 32 + tx] = o;
        }
    }
}

__device__ __forceinline__ float4 bf4_to_f4(uint2 u) {
    __nv_bfloat162 a = *reinterpret_cast<__nv_bfloat162*>(&u.x);
    __nv_bfloat162 b = *reinterpret_cast<__nv_bfloat162*>(&u.y);
    float2 fa = __bfloat1622float2(a);
    float2 fb = __bfloat1622float2(b);
    return make_float4(fa.x, fa.y, fb.x, fb.y);
}

// -------- fused gather: B[c,:] = relu( dinv[c]*(A'[c] + sum_in A'[r]) + b ) ----
// One warp per destination node; lane owns 4 bf16 (8 B) of the row.
__global__ __launch_bounds__(256) void k_gather(const __nv_bfloat16* __restrict__ Ap,
                                                float* __restrict__ B,
                                                const float* __restrict__ bias,
                                                int n) {
    int lane = threadIdx.x & 31;
    int node = (blockIdx.x * blockDim.x + threadIdx.x) >> 5;
    if (node >= n) return;

    const uint2* A2 = reinterpret_cast<const uint2*>(Ap);   // 32 uint2 per row

    // self term A'[node]
    float4 acc = bf4_to_f4(__ldg(&A2[(size_t)node * 32 + lane]));

    int e = g_rowptr[node];
    int end = g_rowptr[node + 1];

    for (; e + 4 <= end; e += 4) {
        int r0 = __ldg(&g_src[e + 0]);
        int r1 = __ldg(&g_src[e + 1]);
        int r2 = __ldg(&g_src[e + 2]);
        int r3 = __ldg(&g_src[e + 3]);
        float4 v0 = bf4_to_f4(__ldg(&A2[(size_t)r0 * 32 + lane]));
        float4 v1 = bf4_to_f4(__ldg(&A2[(size_t)r1 * 32 + lane]));
        float4 v2 = bf4_to_f4(__ldg(&A2[(size_t)r2 * 32 + lane]));
        float4 v3 = bf4_to_f4(__ldg(&A2[(size_t)r3 * 32 + lane]));
        acc.x += v0.x + v1.x + v2.x + v3.x;
        acc.y += v0.y + v1.y + v2.y + v3.y;
        acc.z += v0.z + v1.z + v2.z + v3.z;
        acc.w += v0.w + v1.w + v2.w + v3.w;
    }
    for (; e < end; ++e) {
        int r = __ldg(&g_src[e]);
        float4 v = bf4_to_f4(__ldg(&A2[(size_t)r * 32 + lane]));
        acc.x += v.x; acc.y += v.y; acc.z += v.z; acc.w += v.w;
    }

    float dc = __ldg(&g_dinv[node]);
    float4 bb = __ldg(reinterpret_cast<const float4*>(bias) + lane);
    acc.x = fmaxf(fmaf(acc.x, dc, bb.x), 0.f);
    acc.y = fmaxf(fmaf(acc.y, dc, bb.y), 0.f);
    acc.z = fmaxf(fmaf(acc.z, dc, bb.z), 0.f);
    acc.w = fmaxf(fmaf(acc.w, dc, bb.w), 0.f);
    reinterpret_cast<float4*>(B)[(size_t)node * 32 + lane] = acc;
}

// ---------------- mean pool (sum via atomics; divide in head) ----------------
__global__ void k_pool(const float* __restrict__ H, const int* __restrict__ batch, int n) {
    int lane = threadIdx.x & 31;
    int node = (blockIdx.x * blockDim.x + threadIdx.x) >> 5;
    if (node >= n) return;
    int b = __ldg(&batch[node]);
    float4 v = __ldg(reinterpret_cast<const float4*>(H + (size_t)node * DH) + lane);
    float* p = g_pooled + (size_t)b * DH + (lane << 2);
    asm volatile("red.global.add.v4.f32 [%0], {%1, %2, %3, %4};"
                 :: "l"(p), "f"(v.x), "f"(v.y), "f"(v.z), "f"(v.w) : "memory");
    if (lane == 0) atomicAdd(&g_cnt[b], 1);
}

// ---------------- head: logits = (pooled/cnt) @ Wout + bout; log_softmax -----
__global__ void k_head(const float* __restrict__ Wout, const float* __restrict__ bout,
                       float* __restrict__ out, int G) {
    int g = blockIdx.x * blockDim.x + threadIdx.x;
    if (g >= G) return;
    float inv = 1.0f / fmaxf((float)g_cnt[g], 1.0f);
    float logit[10];
    #pragma unroll
    for (int c = 0; c < 10; ++c) logit[c] = bout[c];
    for (int k = 0; k < DH; ++k) {
        float p = g_pooled[g * DH + k] * inv;
        #pragma unroll
        for (int c = 0; c < 10; ++c) logit[c] = fmaf(p, Wout[k * 10 + c], logit[c]);
    }
    float m = logit[0];
    #pragma unroll
    for (int c = 1; c < 10; ++c) m = fmaxf(m, logit[c]);
    float s = 0.f;
    #pragma unroll
    for (int c = 0; c < 10; ++c) s += expf(logit[c] - m);
    float lse = m + logf(s);
    #pragma unroll
    for (int c = 0; c < 10; ++c) out[g * 10 + c] = logit[c] - lse;
}

extern "C" void kernel_launch(void* const* d_in, const int* in_sizes, int n_in,
                              void* d_out, int out_size) {
    const float* x    = (const float*)d_in[0];
    const float* W1   = (const float*)d_in[1];
    const float* b1   = (const float*)d_in[2];
    const float* W2   = (const float*)d_in[3];
    const float* b2   = (const float*)d_in[4];
    const float* Wout = (const float*)d_in[5];
    const float* bout = (const float*)d_in[6];
    const int*   ei   = (const int*)d_in[7];
    const int*   batch= (const int*)d_in[8];
    float* out = (float*)d_out;

    int n = in_sizes[0] / DH;
    int E = in_sizes[7] / 2;
    int G = out_size / 10;
    const int* row = ei;
    const int* col = ei + E;

    __nv_bfloat16* A;
    float* B;
    cudaGetSymbolAddress((void**)&A, g_Abf);
    cudaGetSymbolAddress((void**)&B, g_B);

    const int smemGemm = (DH * DH + 64 * DH) * sizeof(float);   // 96 KB
    cudaFuncSetAttribute(k_gemm, cudaFuncAttributeMaxDynamicSharedMemorySize, smemGemm);

    // ---- graph preprocessing (CSR by destination) ----
    int resetTot = n > G * DH ? n : G * DH;
    k_reset<<<(resetTot + 255) / 256, 256>>>(n, G);
    k_deg_count<<<(E + 255) / 256, 256>>>(col, E);
    k_dinv<<<(n + 255) / 256, 256>>>(n);

    int nb = (n + SCAN_TILE - 1) / SCAN_TILE;
    k_scanA<<<nb, 256>>>(n);
    k_scanB<<<1, 128>>>(nb, n);
    k_scanC<<<nb, 256>>>(n);
    k_fill<<<(E + 255) / 256, 256>>>(row, col, E);

    int gemmBlocks = (n + 63) / 64;
    int warpBlocks = (n * 32 + 255) / 256;

    // Layer 1
    k_gemm<<<gemmBlocks, 256, smemGemm>>>(x, W1, A, n);
    k_gather<<<warpBlocks, 256>>>(A, B, b1, n);

    // Layer 2
    k_gemm<<<gemmBlocks, 256, smemGemm>>>(B, W2, A, n);
    k_gather<<<warpBlocks, 256>>>(A, B, b2, n);

    // Pool + head
    k_pool<<<warpBlocks, 256>>>(B, batch, n);
    k_head<<<(G + 255) / 256, 256>>>(Wout, bout, out, G);
}